// round 2
// baseline (speedup 1.0000x reference)
#include <cuda_runtime.h>
#include <math.h>

// Problem constants
#define Bq   4
#define Nq   1024
#define Cq   512
#define Hq   8
#define HDq  64
#define BHq  32
#define Mq   4096
#define SCALEq 0.125f
#define LN_EPSq 1e-5f

typedef unsigned long long u64;
typedef ulonglong2 u64x2;

// packed fp32x2 FMA (Blackwell sm_103a) — ptxas never emits this from C++
__device__ __forceinline__ u64 f2fma(u64 a, u64 b, u64 c) {
    u64 d;
    asm("fma.rn.f32x2 %0, %1, %2, %3;" : "=l"(d) : "l"(a), "l"(b), "l"(c));
    return d;
}
__device__ __forceinline__ float2 upk(u64 v) {
    float2 r;
    asm("mov.b64 {%0, %1}, %2;" : "=f"(r.x), "=f"(r.y) : "l"(v));
    return r;
}
__device__ __forceinline__ u64 dup2(float x) {
    u64 r;
    asm("mov.b64 %0, {%1, %1};" : "=l"(r) : "f"(x));
    return r;
}

// Scratch (device globals — allocation-free)
__device__ float g_q [BHq * Nq * HDq];   // [bh][n][d]
__device__ float g_k [BHq * Nq * HDq];
__device__ float g_v [BHq * Nq * HDq];
__device__ float g_ao[Mq * Cq];          // attention output [b*n][h*64+d]
__device__ float g_yp[Mq * Cq];          // pre-layernorm y

// ---------------------------------------------------------------------------
// Kernel 1: QKV GEMM. x[4096,512] @ Wqkv[512,1536] + bqkv -> scatter q/k/v
// 128x128x8 tiles, 256 threads, 8x8 per thread, FFMA2 inner loop.
// A staged DUPLICATED in smem so ld.shared.v2.b64 yields (a,a) pairs free.
// ---------------------------------------------------------------------------
__global__ __launch_bounds__(256) void k_qkv(const float* __restrict__ A,
                                             const float* __restrict__ Bm,
                                             const float* __restrict__ bias) {
    const int K = 512, Nn = 1536;
    __shared__ float As[8][256];   // duplicated along rows
    __shared__ float Bs[8][128];
    int tid = threadIdx.x;
    int bx = blockIdx.x, by = blockIdx.y;
    int aRow = tid >> 1, aCol = (tid & 1) << 2;
    int bRow = tid >> 5, bCol = (tid & 31) << 2;
    int ty = tid >> 4, tx = tid & 15;

    u64 acc[8][4];
#pragma unroll
    for (int i = 0; i < 8; i++)
#pragma unroll
        for (int j = 0; j < 4; j++) acc[i][j] = 0ULL;

    const float* Ap = A + (size_t)(by * 128 + aRow) * K + aCol;
    const float* Bp = Bm + (size_t)bRow * Nn + bx * 128 + bCol;

    for (int k0 = 0; k0 < K; k0 += 8) {
        float4 av = *(const float4*)(Ap + k0);
        As[aCol + 0][2 * aRow] = av.x; As[aCol + 0][2 * aRow + 1] = av.x;
        As[aCol + 1][2 * aRow] = av.y; As[aCol + 1][2 * aRow + 1] = av.y;
        As[aCol + 2][2 * aRow] = av.z; As[aCol + 2][2 * aRow + 1] = av.z;
        As[aCol + 3][2 * aRow] = av.w; As[aCol + 3][2 * aRow + 1] = av.w;
        *(float4*)&Bs[bRow][bCol] = *(const float4*)(Bp + (size_t)k0 * Nn);
        __syncthreads();
#pragma unroll
        for (int k = 0; k < 8; k++) {
            u64x2 a0 = *(const u64x2*)&As[k][ty * 16];       // rows 0,1 dup
            u64x2 a1 = *(const u64x2*)&As[k][ty * 16 + 4];   // rows 2,3
            u64x2 a2 = *(const u64x2*)&As[k][ty * 16 + 8];   // rows 4,5
            u64x2 a3 = *(const u64x2*)&As[k][ty * 16 + 12];  // rows 6,7
            u64x2 b0 = *(const u64x2*)&Bs[k][tx * 8];        // col pairs 0,1
            u64x2 b1 = *(const u64x2*)&Bs[k][tx * 8 + 4];    // col pairs 2,3
            u64 ar[8] = {a0.x, a0.y, a1.x, a1.y, a2.x, a2.y, a3.x, a3.y};
            u64 br[4] = {b0.x, b0.y, b1.x, b1.y};
#pragma unroll
            for (int i = 0; i < 8; i++)
#pragma unroll
                for (int j = 0; j < 4; j++) acc[i][j] = f2fma(ar[i], br[j], acc[i][j]);
        }
        __syncthreads();
    }

#pragma unroll
    for (int i = 0; i < 8; i++) {
        int r = by * 128 + ty * 8 + i;
        int bb = r >> 10, n = r & 1023;
#pragma unroll
        for (int jp = 0; jp < 4; jp++) {
            float2 v2 = upk(acc[i][jp]);
            float vv[2] = {v2.x, v2.y};
#pragma unroll
            for (int l = 0; l < 2; l++) {
                int c = bx * 128 + tx * 8 + jp * 2 + l;
                float v = vv[l] + bias[c];
                int sel = c >> 9;
                int rem = c & 511;
                int h = rem >> 6, d = rem & 63;
                float* dst = (sel == 0) ? g_q : ((sel == 1) ? g_k : g_v);
                dst[((bb * 8 + h) * 1024 + n) * 64 + d] = v;
            }
        }
    }
}

// ---------------------------------------------------------------------------
// Kernel 2: FUSED attention. Block = 32 query rows x full N=1024 for one bh.
// Phase 1: S = poly(q·k^T·scale) -> P in smem (QK via FFMA2)
// Phase 2: row softmax in smem, write attn_final to d_out (single HBM pass)
// Phase 3: O = P·V from smem (FFMA2, k-split 2 groups), write g_ao
// ---------------------------------------------------------------------------
#define PSTR 1028
#define KSTR 260
#define VSTR 68
#define Q_OFF  (32 * PSTR)                 // 32896
#define KV_OFF (Q_OFF + 64 * 64)           // 36992
#define SMF    (KV_OFF + 256 * VSTR)       // 54400 floats = 217600 B

__global__ __launch_bounds__(512) void k_attn(const float* __restrict__ ow_in,
                                              float* __restrict__ attn) {
    extern __shared__ float sm[];
    float* P  = sm;                // [32][1028]
    float* Qt = sm + Q_OFF;        // [64][64]  Q dup-transposed (also PV reduce area)
    float* KV = sm + KV_OFF;       // K: [64][260] transposed / V: [256][68] natural

    int tid = threadIdx.x;
    int bh  = blockIdx.y;
    int m0  = blockIdx.x * 32;

    // softmax(order_weights)
    float w0 = ow_in[0], w1 = ow_in[1], w2 = ow_in[2];
    float mw = fmaxf(w0, fmaxf(w1, w2));
    float e0 = __expf(w0 - mw), e1 = __expf(w1 - mw), e2 = __expf(w2 - mw);
    float winv = 1.f / (e0 + e1 + e2);
    w0 = e0 * winv; w1 = e1 * winv; w2 = e2 * winv;

    // load Q tile dup-transposed: Qt[d][2*row],[2*row+1]
    {
        int row = tid >> 4;
        int d0  = (tid & 15) << 2;
        float4 q = *(const float4*)(g_q + (size_t)(bh * 1024 + m0 + row) * 64 + d0);
        Qt[(d0 + 0) * 64 + 2 * row] = q.x; Qt[(d0 + 0) * 64 + 2 * row + 1] = q.x;
        Qt[(d0 + 1) * 64 + 2 * row] = q.y; Qt[(d0 + 1) * 64 + 2 * row + 1] = q.y;
        Qt[(d0 + 2) * 64 + 2 * row] = q.z; Qt[(d0 + 2) * 64 + 2 * row + 1] = q.z;
        Qt[(d0 + 3) * 64 + 2 * row] = q.w; Qt[(d0 + 3) * 64 + 2 * row + 1] = q.w;
    }

    // ---- Phase 1: QK^T + poly, by 256-col chunks ----
    int ty = tid >> 6;     // 0..7 -> rows ty*4..+3
    int tx = tid & 63;     // cols tx*4..+3 within chunk
    for (int c = 0; c < 4; c++) {
        __syncthreads();
        {   // load K chunk transposed: KV[d][krow]
            int kr = tid >> 1;
            int d0 = (tid & 1) << 5;
            const float* kp = g_k + (size_t)(bh * 1024 + c * 256 + kr) * 64 + d0;
#pragma unroll
            for (int m = 0; m < 8; m++) {
                float4 kv = *(const float4*)(kp + m * 4);
                int d = d0 + m * 4;
                KV[(d + 0) * KSTR + kr] = kv.x;
                KV[(d + 1) * KSTR + kr] = kv.y;
                KV[(d + 2) * KSTR + kr] = kv.z;
                KV[(d + 3) * KSTR + kr] = kv.w;
            }
        }
        __syncthreads();
        u64 acc[4][2];
#pragma unroll
        for (int i = 0; i < 4; i++) { acc[i][0] = 0ULL; acc[i][1] = 0ULL; }
#pragma unroll 8
        for (int d = 0; d < 64; d++) {
            u64x2 a0 = *(const u64x2*)(Qt + d * 64 + ty * 8);      // rows 0,1 dup
            u64x2 a1 = *(const u64x2*)(Qt + d * 64 + ty * 8 + 4);  // rows 2,3 dup
            u64x2 b  = *(const u64x2*)(KV + d * KSTR + tx * 4);    // col pairs
            acc[0][0] = f2fma(a0.x, b.x, acc[0][0]); acc[0][1] = f2fma(a0.x, b.y, acc[0][1]);
            acc[1][0] = f2fma(a0.y, b.x, acc[1][0]); acc[1][1] = f2fma(a0.y, b.y, acc[1][1]);
            acc[2][0] = f2fma(a1.x, b.x, acc[2][0]); acc[2][1] = f2fma(a1.x, b.y, acc[2][1]);
            acc[3][0] = f2fma(a1.y, b.x, acc[3][0]); acc[3][1] = f2fma(a1.y, b.y, acc[3][1]);
        }
#pragma unroll
        for (int i = 0; i < 4; i++) {
            float2 v0 = upk(acc[i][0]);
            float2 v1 = upk(acc[i][1]);
            float4 o; float s;
            s = v0.x * SCALEq; o.x = s * (w0 + s * (w1 + s * w2));
            s = v0.y * SCALEq; o.y = s * (w0 + s * (w1 + s * w2));
            s = v1.x * SCALEq; o.z = s * (w0 + s * (w1 + s * w2));
            s = v1.y * SCALEq; o.w = s * (w0 + s * (w1 + s * w2));
            *(float4*)(P + (ty * 4 + i) * PSTR + c * 256 + tx * 4) = o;
        }
    }
    __syncthreads();

    // ---- Phase 2: row softmax in smem + single write of attn_final ----
    {
        int w = tid >> 5, lane = tid & 31;
#pragma unroll
        for (int rr = 0; rr < 2; rr++) {
            int r = w * 2 + rr;
            float* pr = P + r * PSTR;
            float m = -3.0e38f;
#pragma unroll
            for (int it = 0; it < 32; it++) m = fmaxf(m, pr[lane + it * 32]);
#pragma unroll
            for (int o = 16; o; o >>= 1) m = fmaxf(m, __shfl_xor_sync(0xffffffffu, m, o));
            float sme = 0.f;
#pragma unroll
            for (int it = 0; it < 32; it++) {
                float e = __expf(pr[lane + it * 32] - m);
                pr[lane + it * 32] = e;
                sme += e;
            }
#pragma unroll
            for (int o = 16; o; o >>= 1) sme += __shfl_xor_sync(0xffffffffu, sme, o);
            float inv2 = 1.f / sme;
            float* ar = attn + (size_t)(bh * 1024 + m0 + r) * 1024;
#pragma unroll
            for (int it = 0; it < 32; it++) {
                float e = pr[lane + it * 32] * inv2;
                pr[lane + it * 32] = e;
                ar[lane + it * 32] = e;
            }
        }
    }

    // ---- Phase 3: O = P @ V, k-split into 2 groups of 256 threads ----
    {
        int g   = tid >> 8;          // 0..1 (k partition)
        int r   = (tid >> 3) & 31;   // row 0..31
        int tx8 = tid & 7;           // cols tx8*8..+7
        u64 acc[4] = {0ULL, 0ULL, 0ULL, 0ULL};
        for (int c = 0; c < 4; c++) {
            __syncthreads();
            {   // load V chunk natural: KV[vrow][d] stride VSTR
                int vr = tid >> 1;
                int d0 = (tid & 1) << 5;
                const float* vp = g_v + (size_t)(bh * 1024 + c * 256 + vr) * 64 + d0;
                float* vd = KV + vr * VSTR + d0;
#pragma unroll
                for (int m = 0; m < 8; m++)
                    *(float4*)(vd + m * 4) = *(const float4*)(vp + m * 4);
            }
            __syncthreads();
            const float* pr = P + r * PSTR + c * 256 + g * 128;
            const float* vb = KV + (g * 128) * VSTR + tx8 * 8;
#pragma unroll 4
            for (int k = 0; k < 128; k++) {
                u64 p2 = dup2(pr[k]);
                u64x2 v0 = *(const u64x2*)(vb + k * VSTR);
                u64x2 v1 = *(const u64x2*)(vb + k * VSTR + 4);
                acc[0] = f2fma(p2, v0.x, acc[0]);
                acc[1] = f2fma(p2, v0.y, acc[1]);
                acc[2] = f2fma(p2, v1.x, acc[2]);
                acc[3] = f2fma(p2, v1.y, acc[3]);
            }
        }
        __syncthreads();
        float* red = Qt;   // reuse: 2048 floats needed
        if (g == 1) {
            float* dst = red + r * 64 + tx8 * 8;
#pragma unroll
            for (int jj = 0; jj < 4; jj++) {
                float2 v = upk(acc[jj]);
                dst[jj * 2 + 0] = v.x;
                dst[jj * 2 + 1] = v.y;
            }
        }
        __syncthreads();
        if (g == 0) {
            const float* src = red + r * 64 + tx8 * 8;
            int b = bh >> 3, h = bh & 7;
            float* op = g_ao + (size_t)(b * 1024 + m0 + r) * 512 + h * 64 + tx8 * 8;
#pragma unroll
            for (int jj = 0; jj < 4; jj++) {
                float2 v = upk(acc[jj]);
                op[jj * 2 + 0] = v.x + src[jj * 2 + 0];
                op[jj * 2 + 1] = v.y + src[jj * 2 + 1];
            }
        }
    }
}

// ---------------------------------------------------------------------------
// Kernel 3: proj GEMM + bias + residual (FFMA2). g_ao[4096,512] @ Wproj[512,512]
// ---------------------------------------------------------------------------
__global__ __launch_bounds__(256) void k_proj(const float* __restrict__ x,
                                              const float* __restrict__ Bm,
                                              const float* __restrict__ bias) {
    const int K = 512, Nn = 512;
    __shared__ float As[8][256];
    __shared__ float Bs[8][128];
    int tid = threadIdx.x;
    int bx = blockIdx.x, by = blockIdx.y;
    int aRow = tid >> 1, aCol = (tid & 1) << 2;
    int bRow = tid >> 5, bCol = (tid & 31) << 2;
    int ty = tid >> 4, tx = tid & 15;

    u64 acc[8][4];
#pragma unroll
    for (int i = 0; i < 8; i++)
#pragma unroll
        for (int j = 0; j < 4; j++) acc[i][j] = 0ULL;

    const float* Ap = g_ao + (size_t)(by * 128 + aRow) * K + aCol;
    const float* Bp = Bm + (size_t)bRow * Nn + bx * 128 + bCol;

    for (int k0 = 0; k0 < K; k0 += 8) {
        float4 av = *(const float4*)(Ap + k0);
        As[aCol + 0][2 * aRow] = av.x; As[aCol + 0][2 * aRow + 1] = av.x;
        As[aCol + 1][2 * aRow] = av.y; As[aCol + 1][2 * aRow + 1] = av.y;
        As[aCol + 2][2 * aRow] = av.z; As[aCol + 2][2 * aRow + 1] = av.z;
        As[aCol + 3][2 * aRow] = av.w; As[aCol + 3][2 * aRow + 1] = av.w;
        *(float4*)&Bs[bRow][bCol] = *(const float4*)(Bp + (size_t)k0 * Nn);
        __syncthreads();
#pragma unroll
        for (int k = 0; k < 8; k++) {
            u64x2 a0 = *(const u64x2*)&As[k][ty * 16];
            u64x2 a1 = *(const u64x2*)&As[k][ty * 16 + 4];
            u64x2 a2 = *(const u64x2*)&As[k][ty * 16 + 8];
            u64x2 a3 = *(const u64x2*)&As[k][ty * 16 + 12];
            u64x2 b0 = *(const u64x2*)&Bs[k][tx * 8];
            u64x2 b1 = *(const u64x2*)&Bs[k][tx * 8 + 4];
            u64 ar[8] = {a0.x, a0.y, a1.x, a1.y, a2.x, a2.y, a3.x, a3.y};
            u64 br[4] = {b0.x, b0.y, b1.x, b1.y};
#pragma unroll
            for (int i = 0; i < 8; i++)
#pragma unroll
                for (int j = 0; j < 4; j++) acc[i][j] = f2fma(ar[i], br[j], acc[i][j]);
        }
        __syncthreads();
    }

#pragma unroll
    for (int i = 0; i < 8; i++) {
        int r = by * 128 + ty * 8 + i;
#pragma unroll
        for (int jp = 0; jp < 4; jp++) {
            float2 v2 = upk(acc[i][jp]);
            int c = bx * 128 + tx * 8 + jp * 2;
            g_yp[(size_t)r * 512 + c]     = v2.x + bias[c]     + x[(size_t)r * 512 + c];
            g_yp[(size_t)r * 512 + c + 1] = v2.y + bias[c + 1] + x[(size_t)r * 512 + c + 1];
        }
    }
}

// ---------------------------------------------------------------------------
// Kernel 4: LayerNorm over last dim (512)
// ---------------------------------------------------------------------------
__global__ __launch_bounds__(128) void k_ln(const float* __restrict__ gamma,
                                            const float* __restrict__ beta,
                                            float* __restrict__ y) {
    __shared__ float s1[4], s2[4];
    int row = blockIdx.x;
    int tid = threadIdx.x;
    const float* p = g_yp + (size_t)row * 512;
    float4 v = *(const float4*)(p + tid * 4);

    float s = v.x + v.y + v.z + v.w;
    float ss = v.x * v.x + v.y * v.y + v.z * v.z + v.w * v.w;
#pragma unroll
    for (int o = 16; o; o >>= 1) {
        s += __shfl_xor_sync(0xffffffffu, s, o);
        ss += __shfl_xor_sync(0xffffffffu, ss, o);
    }
    int wid = tid >> 5, lane = tid & 31;
    if (lane == 0) { s1[wid] = s; s2[wid] = ss; }
    __syncthreads();
    if (tid == 0) {
        s1[0] = s1[0] + s1[1] + s1[2] + s1[3];
        s2[0] = s2[0] + s2[1] + s2[2] + s2[3];
    }
    __syncthreads();
    float mu = s1[0] * (1.f / 512.f);
    float var = s2[0] * (1.f / 512.f) - mu * mu;
    float rstd = rsqrtf(var + LN_EPSq);

    int c = tid * 4;
    float4 g = *(const float4*)(gamma + c);
    float4 be = *(const float4*)(beta + c);
    float4 o;
    o.x = (v.x - mu) * rstd * g.x + be.x;
    o.y = (v.y - mu) * rstd * g.y + be.y;
    o.z = (v.z - mu) * rstd * g.z + be.z;
    o.w = (v.w - mu) * rstd * g.w + be.w;
    *(float4*)(y + (size_t)row * 512 + c) = o;
}

// ---------------------------------------------------------------------------
extern "C" void kernel_launch(void* const* d_in, const int* in_sizes, int n_in,
                              void* d_out, int out_size) {
    (void)in_sizes; (void)n_in; (void)out_size;
    const float* x     = (const float*)d_in[0];
    const float* Wqkv  = (const float*)d_in[1];
    const float* bqkv  = (const float*)d_in[2];
    const float* ow    = (const float*)d_in[3];
    const float* Wproj = (const float*)d_in[4];
    const float* bproj = (const float*)d_in[5];
    const float* gamma = (const float*)d_in[6];
    const float* beta  = (const float*)d_in[7];

    float* out      = (float*)d_out;
    float* y_out    = out;                         // [4,1024,512]
    float* attn_out = out + (size_t)Bq * Nq * Cq;  // [4,8,1024,1024]

    cudaFuncSetAttribute(k_attn, cudaFuncAttributeMaxDynamicSharedMemorySize,
                         SMF * (int)sizeof(float));

    k_qkv <<<dim3(12, 32), 256>>>(x, Wqkv, bqkv);
    k_attn<<<dim3(32, 32), 512, SMF * sizeof(float)>>>(ow, attn_out);
    k_proj<<<dim3(4, 32), 256>>>(x, Wproj, bproj);
    k_ln  <<<4096, 128>>>(gamma, beta, y_out);
}

// round 3
// speedup vs baseline: 1.9797x; 1.9797x over previous
#include <cuda_runtime.h>
#include <math.h>

// Problem constants
#define Bq   4
#define Nq   1024
#define Cq   512
#define Hq   8
#define HDq  64
#define BHq  32
#define Mq   4096
#define SCALEq 0.125f
#define LN_EPSq 1e-5f

// Scratch (device globals — allocation-free)
__device__ float g_q [BHq * Nq * HDq];   // [bh][n][d]
__device__ float g_k [BHq * Nq * HDq];
__device__ float g_v [BHq * Nq * HDq];
__device__ float g_ao[Mq * Cq];          // attention output [b*n][h*64+d]
__device__ float g_yp[Mq * Cq];          // pre-layernorm y

// ---------------------------------------------------------------------------
// Kernel 1: QKV GEMM. x[4096,512] @ Wqkv[512,1536] + bqkv -> scatter q/k/v
// 128x128x8 tiles, 256 threads, 8x8/thread, ping-pong double-buffered smem.
// ---------------------------------------------------------------------------
__global__ __launch_bounds__(256) void k_qkv(const float* __restrict__ A,
                                             const float* __restrict__ Bm,
                                             const float* __restrict__ bias) {
    const int K = 512, Nn = 1536;
    __shared__ float As[2][8][128];
    __shared__ float Bs[2][8][128];
    int tid = threadIdx.x;
    int bx = blockIdx.x, by = blockIdx.y;
    int aRow = tid >> 1, aCol = (tid & 1) << 2;
    int bRow = tid >> 5, bCol = (tid & 31) << 2;
    int ty = tid >> 4, tx = tid & 15;

    float acc[8][8];
#pragma unroll
    for (int i = 0; i < 8; i++)
#pragma unroll
        for (int j = 0; j < 8; j++) acc[i][j] = 0.f;

    const float* Ap = A + (size_t)(by * 128 + aRow) * K + aCol;
    const float* Bp = Bm + (size_t)bRow * Nn + bx * 128 + bCol;

    // prologue: load slab 0 into buffer 0
    {
        float4 av = *(const float4*)(Ap);
        As[0][aCol + 0][aRow] = av.x;
        As[0][aCol + 1][aRow] = av.y;
        As[0][aCol + 2][aRow] = av.z;
        As[0][aCol + 3][aRow] = av.w;
        *(float4*)&Bs[0][bRow][bCol] = *(const float4*)(Bp);
    }
    __syncthreads();

    for (int k0 = 0; k0 < K; k0 += 8) {
        int buf = (k0 >> 3) & 1;
        float4 av, bv;
        bool more = (k0 + 8) < K;
        if (more) {
            av = *(const float4*)(Ap + k0 + 8);
            bv = *(const float4*)(Bp + (size_t)(k0 + 8) * Nn);
        }
#pragma unroll
        for (int k = 0; k < 8; k++) {
            float a[8], b[8];
            *(float4*)&a[0] = *(const float4*)&As[buf][k][ty * 8];
            *(float4*)&a[4] = *(const float4*)&As[buf][k][ty * 8 + 4];
            *(float4*)&b[0] = *(const float4*)&Bs[buf][k][tx * 8];
            *(float4*)&b[4] = *(const float4*)&Bs[buf][k][tx * 8 + 4];
#pragma unroll
            for (int i = 0; i < 8; i++)
#pragma unroll
                for (int j = 0; j < 8; j++) acc[i][j] = fmaf(a[i], b[j], acc[i][j]);
        }
        if (more) {
            int nb = buf ^ 1;
            As[nb][aCol + 0][aRow] = av.x;
            As[nb][aCol + 1][aRow] = av.y;
            As[nb][aCol + 2][aRow] = av.z;
            As[nb][aCol + 3][aRow] = av.w;
            *(float4*)&Bs[nb][bRow][bCol] = bv;
        }
        __syncthreads();
    }

    // epilogue: scatter into q/k/v [bh][n][d]
#pragma unroll
    for (int i = 0; i < 8; i++) {
        int r = by * 128 + ty * 8 + i;
        int bb = r >> 10, n = r & 1023;
#pragma unroll
        for (int j = 0; j < 8; j++) {
            int c = bx * 128 + tx * 8 + j;
            float v = acc[i][j] + bias[c];
            int sel = c >> 9;
            int rem = c & 511;
            int h = rem >> 6, d = rem & 63;
            float* dst = (sel == 0) ? g_q : ((sel == 1) ? g_k : g_v);
            dst[((bb * 8 + h) * 1024 + n) * 64 + d] = v;
        }
    }
}

// ---------------------------------------------------------------------------
// Kernel 2: scores. S = poly(ow; q·k^T*SCALE) pre-softmax into attn.
// 128x128 tile per block per bh, 256 threads, 8x8/thread, K=64 fully resident.
// Dynamic smem: Qt[64][132] + Kt[64][132] transposed = 67584 B.
// ---------------------------------------------------------------------------
#define QKSTR 132
__global__ __launch_bounds__(256) void k_scores(const float* __restrict__ ow_in,
                                                float* __restrict__ attn) {
    extern __shared__ float sm[];
    float* Qt = sm;                // [d][row]
    float* Kt = sm + 64 * QKSTR;   // [d][col]
    int bh = blockIdx.z;
    int mb = blockIdx.y * 128;
    int nb = blockIdx.x * 128;
    int tid = threadIdx.x;

    // load Q,K tiles transposed: 128 rows x 64 d each
    {
        int row = tid >> 1;
        int d0 = (tid & 1) << 5;
        const float* qp = g_q + (size_t)(bh * 1024 + mb + row) * 64 + d0;
        const float* kp = g_k + (size_t)(bh * 1024 + nb + row) * 64 + d0;
#pragma unroll
        for (int m = 0; m < 8; m++) {
            int d = d0 + m * 4;
            float4 qv = *(const float4*)(qp + m * 4);
            Qt[(d + 0) * QKSTR + row] = qv.x;
            Qt[(d + 1) * QKSTR + row] = qv.y;
            Qt[(d + 2) * QKSTR + row] = qv.z;
            Qt[(d + 3) * QKSTR + row] = qv.w;
            float4 kv = *(const float4*)(kp + m * 4);
            Kt[(d + 0) * QKSTR + row] = kv.x;
            Kt[(d + 1) * QKSTR + row] = kv.y;
            Kt[(d + 2) * QKSTR + row] = kv.z;
            Kt[(d + 3) * QKSTR + row] = kv.w;
        }
    }
    __syncthreads();

    int ty = tid >> 4, tx = tid & 15;
    float acc[8][8];
#pragma unroll
    for (int i = 0; i < 8; i++)
#pragma unroll
        for (int j = 0; j < 8; j++) acc[i][j] = 0.f;

#pragma unroll 8
    for (int d = 0; d < 64; d++) {
        float a[8], b[8];
        *(float4*)&a[0] = *(const float4*)(Qt + d * QKSTR + ty * 8);
        *(float4*)&a[4] = *(const float4*)(Qt + d * QKSTR + ty * 8 + 4);
        *(float4*)&b[0] = *(const float4*)(Kt + d * QKSTR + tx * 8);
        *(float4*)&b[4] = *(const float4*)(Kt + d * QKSTR + tx * 8 + 4);
#pragma unroll
        for (int i = 0; i < 8; i++)
#pragma unroll
            for (int j = 0; j < 8; j++) acc[i][j] = fmaf(a[i], b[j], acc[i][j]);
    }

    // softmax(order_weights)
    float w0 = ow_in[0], w1 = ow_in[1], w2 = ow_in[2];
    float mw = fmaxf(w0, fmaxf(w1, w2));
    float e0 = __expf(w0 - mw), e1 = __expf(w1 - mw), e2 = __expf(w2 - mw);
    float inv = 1.f / (e0 + e1 + e2);
    w0 = e0 * inv; w1 = e1 * inv; w2 = e2 * inv;

#pragma unroll
    for (int i = 0; i < 8; i++) {
        int row = bh * 1024 + mb + ty * 8 + i;
        float o[8];
#pragma unroll
        for (int j = 0; j < 8; j++) {
            float s = acc[i][j] * SCALEq;
            o[j] = s * (w0 + s * (w1 + s * w2));
        }
        float* dst = attn + (size_t)row * 1024 + nb + tx * 8;
        *(float4*)dst = *(float4*)&o[0];
        *(float4*)(dst + 4) = *(float4*)&o[4];
    }
}

// ---------------------------------------------------------------------------
// Kernel 3: row softmax in place on attn [32768 rows x 1024].
// ---------------------------------------------------------------------------
__global__ __launch_bounds__(256) void k_softmax(float* __restrict__ attn) {
    __shared__ float red[8];
    int row = blockIdx.x;
    int tid = threadIdx.x;
    float* p = attn + (size_t)row * 1024;
    float4 v = *(const float4*)(p + tid * 4);

    float m = fmaxf(fmaxf(v.x, v.y), fmaxf(v.z, v.w));
#pragma unroll
    for (int o = 16; o; o >>= 1) m = fmaxf(m, __shfl_xor_sync(0xffffffffu, m, o));
    int wid = tid >> 5, lane = tid & 31;
    if (lane == 0) red[wid] = m;
    __syncthreads();
    if (tid == 0) {
        float mm = red[0];
#pragma unroll
        for (int i = 1; i < 8; i++) mm = fmaxf(mm, red[i]);
        red[0] = mm;
    }
    __syncthreads();
    m = red[0];
    __syncthreads();

    float4 e;
    e.x = __expf(v.x - m); e.y = __expf(v.y - m);
    e.z = __expf(v.z - m); e.w = __expf(v.w - m);
    float s = e.x + e.y + e.z + e.w;
#pragma unroll
    for (int o = 16; o; o >>= 1) s += __shfl_xor_sync(0xffffffffu, s, o);
    if (lane == 0) red[wid] = s;
    __syncthreads();
    if (tid == 0) {
        float ss = 0.f;
#pragma unroll
        for (int i = 0; i < 8; i++) ss += red[i];
        red[0] = ss;
    }
    __syncthreads();
    float invs = 1.f / red[0];

    e.x *= invs; e.y *= invs; e.z *= invs; e.w *= invs;
    *(float4*)(p + tid * 4) = e;
}

// ---------------------------------------------------------------------------
// Kernel 4: out = attn @ V.  Per (b,h): [1024,1024]@[1024,64].
// 64-row x 64-col tile, 128 threads, 8x4/thread.
// ---------------------------------------------------------------------------
#define AVSTR 68
__global__ __launch_bounds__(128) void k_av(const float* __restrict__ attn) {
    __shared__ float At[64 * AVSTR];  // [k][row] transposed attn tile
    __shared__ float Vs[64 * AVSTR];  // [k][d]   natural V tile
    int mb = blockIdx.x * 64;
    int bh = blockIdx.y;
    int tid = threadIdx.x;
    int hrow = tid >> 1;              // 0..63
    int hc0 = (tid & 1) << 5;         // 0 or 32
    int ty = tid >> 4;                // 0..7 -> rows ty*8..+7
    int tx = tid & 15;                // cols tx*4..+3

    float acc[8][4];
#pragma unroll
    for (int i = 0; i < 8; i++)
#pragma unroll
        for (int j = 0; j < 4; j++) acc[i][j] = 0.f;

    for (int k0 = 0; k0 < 1024; k0 += 64) {
        // load attn tile transposed: At[k][row]
        const float* ap = attn + (size_t)(bh * 1024 + mb + hrow) * 1024 + k0 + hc0;
#pragma unroll
        for (int m = 0; m < 8; m++) {
            float4 av = *(const float4*)(ap + m * 4);
            int kk = hc0 + m * 4;
            At[(kk + 0) * AVSTR + hrow] = av.x;
            At[(kk + 1) * AVSTR + hrow] = av.y;
            At[(kk + 2) * AVSTR + hrow] = av.z;
            At[(kk + 3) * AVSTR + hrow] = av.w;
        }
        // load V tile natural: Vs[k][d]
        const float* vp = g_v + (size_t)(bh * 1024 + k0 + hrow) * 64 + hc0;
        float* vd = Vs + hrow * AVSTR + hc0;
#pragma unroll
        for (int m = 0; m < 8; m++)
            *(float4*)(vd + m * 4) = *(const float4*)(vp + m * 4);
        __syncthreads();

#pragma unroll 8
        for (int kk = 0; kk < 64; kk++) {
            float a[8], b[4];
            *(float4*)&a[0] = *(const float4*)(At + kk * AVSTR + ty * 8);
            *(float4*)&a[4] = *(const float4*)(At + kk * AVSTR + ty * 8 + 4);
            *(float4*)&b[0] = *(const float4*)(Vs + kk * AVSTR + tx * 4);
#pragma unroll
            for (int i = 0; i < 8; i++)
#pragma unroll
                for (int j = 0; j < 4; j++) acc[i][j] = fmaf(a[i], b[j], acc[i][j]);
        }
        __syncthreads();
    }

    int b = bh >> 3, h = bh & 7;
#pragma unroll
    for (int i = 0; i < 8; i++) {
        int n = mb + ty * 8 + i;
        float4 o = {acc[i][0], acc[i][1], acc[i][2], acc[i][3]};
        *(float4*)(g_ao + (size_t)(b * 1024 + n) * 512 + h * 64 + tx * 4) = o;
    }
}

// ---------------------------------------------------------------------------
// Kernel 5: proj GEMM + bias + residual. g_ao[4096,512] @ Wproj[512,512]
// 128x128x8 tiles, ping-pong double-buffered.
// ---------------------------------------------------------------------------
__global__ __launch_bounds__(256) void k_proj(const float* __restrict__ x,
                                              const float* __restrict__ Bm,
                                              const float* __restrict__ bias) {
    const int K = 512, Nn = 512;
    __shared__ float As[2][8][128];
    __shared__ float Bs[2][8][128];
    int tid = threadIdx.x;
    int bx = blockIdx.x, by = blockIdx.y;
    int aRow = tid >> 1, aCol = (tid & 1) << 2;
    int bRow = tid >> 5, bCol = (tid & 31) << 2;
    int ty = tid >> 4, tx = tid & 15;

    float acc[8][8];
#pragma unroll
    for (int i = 0; i < 8; i++)
#pragma unroll
        for (int j = 0; j < 8; j++) acc[i][j] = 0.f;

    const float* Ap = g_ao + (size_t)(by * 128 + aRow) * K + aCol;
    const float* Bp = Bm + (size_t)bRow * Nn + bx * 128 + bCol;

    {
        float4 av = *(const float4*)(Ap);
        As[0][aCol + 0][aRow] = av.x;
        As[0][aCol + 1][aRow] = av.y;
        As[0][aCol + 2][aRow] = av.z;
        As[0][aCol + 3][aRow] = av.w;
        *(float4*)&Bs[0][bRow][bCol] = *(const float4*)(Bp);
    }
    __syncthreads();

    for (int k0 = 0; k0 < K; k0 += 8) {
        int buf = (k0 >> 3) & 1;
        float4 av, bv;
        bool more = (k0 + 8) < K;
        if (more) {
            av = *(const float4*)(Ap + k0 + 8);
            bv = *(const float4*)(Bp + (size_t)(k0 + 8) * Nn);
        }
#pragma unroll
        for (int k = 0; k < 8; k++) {
            float a[8], b[8];
            *(float4*)&a[0] = *(const float4*)&As[buf][k][ty * 8];
            *(float4*)&a[4] = *(const float4*)&As[buf][k][ty * 8 + 4];
            *(float4*)&b[0] = *(const float4*)&Bs[buf][k][tx * 8];
            *(float4*)&b[4] = *(const float4*)&Bs[buf][k][tx * 8 + 4];
#pragma unroll
            for (int i = 0; i < 8; i++)
#pragma unroll
                for (int j = 0; j < 8; j++) acc[i][j] = fmaf(a[i], b[j], acc[i][j]);
        }
        if (more) {
            int nb2 = buf ^ 1;
            As[nb2][aCol + 0][aRow] = av.x;
            As[nb2][aCol + 1][aRow] = av.y;
            As[nb2][aCol + 2][aRow] = av.z;
            As[nb2][aCol + 3][aRow] = av.w;
            *(float4*)&Bs[nb2][bRow][bCol] = bv;
        }
        __syncthreads();
    }

#pragma unroll
    for (int i = 0; i < 8; i++) {
        int r = by * 128 + ty * 8 + i;
#pragma unroll
        for (int j = 0; j < 8; j++) {
            int c = bx * 128 + tx * 8 + j;
            g_yp[(size_t)r * 512 + c] = acc[i][j] + bias[c] + x[(size_t)r * 512 + c];
        }
    }
}

// ---------------------------------------------------------------------------
// Kernel 6: LayerNorm over last dim (512), write y to d_out.
// ---------------------------------------------------------------------------
__global__ __launch_bounds__(128) void k_ln(const float* __restrict__ gamma,
                                            const float* __restrict__ beta,
                                            float* __restrict__ y) {
    __shared__ float s1[4], s2[4];
    int row = blockIdx.x;
    int tid = threadIdx.x;
    const float* p = g_yp + (size_t)row * 512;
    float4 v = *(const float4*)(p + tid * 4);

    float s = v.x + v.y + v.z + v.w;
    float ss = v.x * v.x + v.y * v.y + v.z * v.z + v.w * v.w;
#pragma unroll
    for (int o = 16; o; o >>= 1) {
        s += __shfl_xor_sync(0xffffffffu, s, o);
        ss += __shfl_xor_sync(0xffffffffu, ss, o);
    }
    int wid = tid >> 5, lane = tid & 31;
    if (lane == 0) { s1[wid] = s; s2[wid] = ss; }
    __syncthreads();
    if (tid == 0) {
        s1[0] = s1[0] + s1[1] + s1[2] + s1[3];
        s2[0] = s2[0] + s2[1] + s2[2] + s2[3];
    }
    __syncthreads();
    float mu = s1[0] * (1.f / 512.f);
    float var = s2[0] * (1.f / 512.f) - mu * mu;
    float rstd = rsqrtf(var + LN_EPSq);

    int c = tid * 4;
    float4 g = *(const float4*)(gamma + c);
    float4 be = *(const float4*)(beta + c);
    float4 o;
    o.x = (v.x - mu) * rstd * g.x + be.x;
    o.y = (v.y - mu) * rstd * g.y + be.y;
    o.z = (v.z - mu) * rstd * g.z + be.z;
    o.w = (v.w - mu) * rstd * g.w + be.w;
    *(float4*)(y + (size_t)row * 512 + c) = o;
}

// ---------------------------------------------------------------------------
extern "C" void kernel_launch(void* const* d_in, const int* in_sizes, int n_in,
                              void* d_out, int out_size) {
    (void)in_sizes; (void)n_in; (void)out_size;
    const float* x     = (const float*)d_in[0];
    const float* Wqkv  = (const float*)d_in[1];
    const float* bqkv  = (const float*)d_in[2];
    const float* ow    = (const float*)d_in[3];
    const float* Wproj = (const float*)d_in[4];
    const float* bproj = (const float*)d_in[5];
    const float* gamma = (const float*)d_in[6];
    const float* beta  = (const float*)d_in[7];

    float* out      = (float*)d_out;
    float* y_out    = out;                         // [4,1024,512]
    float* attn_out = out + (size_t)Bq * Nq * Cq;  // [4,8,1024,1024]

    int scores_smem = 2 * 64 * QKSTR * (int)sizeof(float);  // 67584 B
    cudaFuncSetAttribute(k_scores, cudaFuncAttributeMaxDynamicSharedMemorySize,
                         scores_smem);

    k_qkv    <<<dim3(12, 32), 256>>>(x, Wqkv, bqkv);
    k_scores <<<dim3(8, 8, 32), 256, scores_smem>>>(ow, attn_out);
    k_softmax<<<32768, 256>>>(attn_out);
    k_av     <<<dim3(16, 32), 128>>>(attn_out);
    k_proj   <<<dim3(4, 32), 256>>>(x, Wproj, bproj);
    k_ln     <<<4096, 128>>>(gamma, beta, y_out);
}

// round 4
// speedup vs baseline: 2.0494x; 1.0352x over previous
#include <cuda_runtime.h>
#include <math.h>

// Problem constants
#define Bq   4
#define Nq   1024
#define Cq   512
#define Hq   8
#define HDq  64
#define BHq  32
#define Mq   4096
#define SCALEq 0.125f
#define LN_EPSq 1e-5f

typedef unsigned long long u64;
typedef ulonglong2 u64x2;

// packed fp32x2 FMA (sm_103a). ptxas never emits this from C++.
__device__ __forceinline__ u64 f2fma(u64 a, u64 b, u64 c) {
    u64 d;
    asm("fma.rn.f32x2 %0, %1, %2, %3;" : "=l"(d) : "l"(a), "l"(b), "l"(c));
    return d;
}
__device__ __forceinline__ float2 upk(u64 v) {
    float2 r;
    asm("mov.b64 {%0, %1}, %2;" : "=f"(r.x), "=f"(r.y) : "l"(v));
    return r;
}
__device__ __forceinline__ u64 dup2(float x) {
    u64 r;
    asm("mov.b64 %0, {%1, %1};" : "=l"(r) : "f"(x));
    return r;
}

// Scratch (device globals — allocation-free)
__device__ float g_q  [BHq * Nq * HDq];     // [bh][n][d]
__device__ float g_k  [BHq * Nq * HDq];
__device__ float g_v  [BHq * Nq * HDq];
__device__ float g_aoP[4 * Mq * Cq];        // 4 k-split partials of attn-out
__device__ float g_yp [Mq * Cq];            // pre-layernorm y

// ---------------------------------------------------------------------------
// Kernel 1: QKV GEMM. x[4096,512] @ Wqkv[512,1536] + bqkv -> scatter q/k/v
// 128x128x8 tiles, 256 threads, 8x8/thread, double-buffered, FFMA2 inner.
// ---------------------------------------------------------------------------
__global__ __launch_bounds__(256) void k_qkv(const float* __restrict__ A,
                                             const float* __restrict__ Bm,
                                             const float* __restrict__ bias) {
    const int K = 512, Nn = 1536;
    __shared__ float As[2][8][128];
    __shared__ float Bs[2][8][128];
    int tid = threadIdx.x;
    int bx = blockIdx.x, by = blockIdx.y;
    int aRow = tid >> 1, aCol = (tid & 1) << 2;
    int bRow = tid >> 5, bCol = (tid & 31) << 2;
    int ty = tid >> 4, tx = tid & 15;

    u64 acc[8][4];
#pragma unroll
    for (int i = 0; i < 8; i++)
#pragma unroll
        for (int j = 0; j < 4; j++) acc[i][j] = 0ULL;

    const float* Ap = A + (size_t)(by * 128 + aRow) * K + aCol;
    const float* Bp = Bm + (size_t)bRow * Nn + bx * 128 + bCol;

    {
        float4 av = *(const float4*)(Ap);
        As[0][aCol + 0][aRow] = av.x;
        As[0][aCol + 1][aRow] = av.y;
        As[0][aCol + 2][aRow] = av.z;
        As[0][aCol + 3][aRow] = av.w;
        *(float4*)&Bs[0][bRow][bCol] = *(const float4*)(Bp);
    }
    __syncthreads();

    for (int k0 = 0; k0 < K; k0 += 8) {
        int buf = (k0 >> 3) & 1;
        float4 av, bv;
        bool more = (k0 + 8) < K;
        if (more) {
            av = *(const float4*)(Ap + k0 + 8);
            bv = *(const float4*)(Bp + (size_t)(k0 + 8) * Nn);
        }
#pragma unroll
        for (int k = 0; k < 8; k++) {
            float a[8];
            *(float4*)&a[0] = *(const float4*)&As[buf][k][ty * 8];
            *(float4*)&a[4] = *(const float4*)&As[buf][k][ty * 8 + 4];
            u64x2 b0 = *(const u64x2*)&Bs[buf][k][tx * 8];
            u64x2 b1 = *(const u64x2*)&Bs[buf][k][tx * 8 + 4];
            u64 bp[4] = {b0.x, b0.y, b1.x, b1.y};
#pragma unroll
            for (int i = 0; i < 8; i++) {
                u64 ad = dup2(a[i]);
#pragma unroll
                for (int j = 0; j < 4; j++) acc[i][j] = f2fma(ad, bp[j], acc[i][j]);
            }
        }
        if (more) {
            int nb = buf ^ 1;
            As[nb][aCol + 0][aRow] = av.x;
            As[nb][aCol + 1][aRow] = av.y;
            As[nb][aCol + 2][aRow] = av.z;
            As[nb][aCol + 3][aRow] = av.w;
            *(float4*)&Bs[nb][bRow][bCol] = bv;
        }
        __syncthreads();
    }

#pragma unroll
    for (int i = 0; i < 8; i++) {
        int r = by * 128 + ty * 8 + i;
        int bb = r >> 10, n = r & 1023;
#pragma unroll
        for (int jp = 0; jp < 4; jp++) {
            float2 v2 = upk(acc[i][jp]);
            float vv[2] = {v2.x, v2.y};
#pragma unroll
            for (int l = 0; l < 2; l++) {
                int c = bx * 128 + tx * 8 + jp * 2 + l;
                float v = vv[l] + bias[c];
                int sel = c >> 9;
                int rem = c & 511;
                int h = rem >> 6, d = rem & 63;
                float* dst = (sel == 0) ? g_q : ((sel == 1) ? g_k : g_v);
                dst[((bb * 8 + h) * 1024 + n) * 64 + d] = v;
            }
        }
    }
}

// ---------------------------------------------------------------------------
// Kernel 2: scores. S = poly(ow; q·k^T*SCALE) pre-softmax into attn.
// 128x128 tile per block per bh, 256 threads, 8x8/thread, FFMA2 inner.
// ---------------------------------------------------------------------------
#define QKSTR 132
__global__ __launch_bounds__(256) void k_scores(const float* __restrict__ ow_in,
                                                float* __restrict__ attn) {
    extern __shared__ float sm[];
    float* Qt = sm;                // [d][row]
    float* Kt = sm + 64 * QKSTR;   // [d][col]
    int bh = blockIdx.z;
    int mb = blockIdx.y * 128;
    int nb = blockIdx.x * 128;
    int tid = threadIdx.x;

    {
        int row = tid >> 1;
        int d0 = (tid & 1) << 5;
        const float* qp = g_q + (size_t)(bh * 1024 + mb + row) * 64 + d0;
        const float* kp = g_k + (size_t)(bh * 1024 + nb + row) * 64 + d0;
#pragma unroll
        for (int m = 0; m < 8; m++) {
            int d = d0 + m * 4;
            float4 qv = *(const float4*)(qp + m * 4);
            Qt[(d + 0) * QKSTR + row] = qv.x;
            Qt[(d + 1) * QKSTR + row] = qv.y;
            Qt[(d + 2) * QKSTR + row] = qv.z;
            Qt[(d + 3) * QKSTR + row] = qv.w;
            float4 kv = *(const float4*)(kp + m * 4);
            Kt[(d + 0) * QKSTR + row] = kv.x;
            Kt[(d + 1) * QKSTR + row] = kv.y;
            Kt[(d + 2) * QKSTR + row] = kv.z;
            Kt[(d + 3) * QKSTR + row] = kv.w;
        }
    }
    __syncthreads();

    int ty = tid >> 4, tx = tid & 15;
    u64 acc[8][4];
#pragma unroll
    for (int i = 0; i < 8; i++)
#pragma unroll
        for (int j = 0; j < 4; j++) acc[i][j] = 0ULL;

#pragma unroll 8
    for (int d = 0; d < 64; d++) {
        float a[8];
        *(float4*)&a[0] = *(const float4*)(Qt + d * QKSTR + ty * 8);
        *(float4*)&a[4] = *(const float4*)(Qt + d * QKSTR + ty * 8 + 4);
        u64x2 b0 = *(const u64x2*)(Kt + d * QKSTR + tx * 8);
        u64x2 b1 = *(const u64x2*)(Kt + d * QKSTR + tx * 8 + 4);
        u64 bp[4] = {b0.x, b0.y, b1.x, b1.y};
#pragma unroll
        for (int i = 0; i < 8; i++) {
            u64 ad = dup2(a[i]);
#pragma unroll
            for (int j = 0; j < 4; j++) acc[i][j] = f2fma(ad, bp[j], acc[i][j]);
        }
    }

    float w0 = ow_in[0], w1 = ow_in[1], w2 = ow_in[2];
    float mw = fmaxf(w0, fmaxf(w1, w2));
    float e0 = __expf(w0 - mw), e1 = __expf(w1 - mw), e2 = __expf(w2 - mw);
    float inv = 1.f / (e0 + e1 + e2);
    w0 = e0 * inv; w1 = e1 * inv; w2 = e2 * inv;

#pragma unroll
    for (int i = 0; i < 8; i++) {
        int row = bh * 1024 + mb + ty * 8 + i;
        float o[8];
#pragma unroll
        for (int jp = 0; jp < 4; jp++) {
            float2 v2 = upk(acc[i][jp]);
            float s;
            s = v2.x * SCALEq; o[jp * 2 + 0] = s * (w0 + s * (w1 + s * w2));
            s = v2.y * SCALEq; o[jp * 2 + 1] = s * (w0 + s * (w1 + s * w2));
        }
        float* dst = attn + (size_t)row * 1024 + nb + tx * 8;
        *(float4*)dst = *(float4*)&o[0];
        *(float4*)(dst + 4) = *(float4*)&o[4];
    }
}

// ---------------------------------------------------------------------------
// Kernel 3: row softmax in place on attn [32768 rows x 1024].
// ---------------------------------------------------------------------------
__global__ __launch_bounds__(256) void k_softmax(float* __restrict__ attn) {
    __shared__ float red[8];
    int row = blockIdx.x;
    int tid = threadIdx.x;
    float* p = attn + (size_t)row * 1024;
    float4 v = *(const float4*)(p + tid * 4);

    float m = fmaxf(fmaxf(v.x, v.y), fmaxf(v.z, v.w));
#pragma unroll
    for (int o = 16; o; o >>= 1) m = fmaxf(m, __shfl_xor_sync(0xffffffffu, m, o));
    int wid = tid >> 5, lane = tid & 31;
    if (lane == 0) red[wid] = m;
    __syncthreads();
    if (tid == 0) {
        float mm = red[0];
#pragma unroll
        for (int i = 1; i < 8; i++) mm = fmaxf(mm, red[i]);
        red[0] = mm;
    }
    __syncthreads();
    m = red[0];
    __syncthreads();

    float4 e;
    e.x = __expf(v.x - m); e.y = __expf(v.y - m);
    e.z = __expf(v.z - m); e.w = __expf(v.w - m);
    float s = e.x + e.y + e.z + e.w;
#pragma unroll
    for (int o = 16; o; o >>= 1) s += __shfl_xor_sync(0xffffffffu, s, o);
    if (lane == 0) red[wid] = s;
    __syncthreads();
    if (tid == 0) {
        float ss = 0.f;
#pragma unroll
        for (int i = 0; i < 8; i++) ss += red[i];
        red[0] = ss;
    }
    __syncthreads();
    float invs = 1.f / red[0];

    e.x *= invs; e.y *= invs; e.z *= invs; e.w *= invs;
    *(float4*)(p + tid * 4) = e;
}

// ---------------------------------------------------------------------------
// Kernel 4: partial AV. Per (b,h,z): [128,256]@[256,64] -> g_aoP[z].
// 256 threads, 128x64 tile, 8x4/thread as 4 ROW-PAIRS x 4 cols (FFMA2;
// row pairs come free from the transposed attn tile, only b needs dup).
// Grid (8, 32, 4) = 1024 blocks -> ~50% occupancy.
// ---------------------------------------------------------------------------
#define ATSTR 132
#define VSTR2 68
__global__ __launch_bounds__(256) void k_av(const float* __restrict__ attn) {
    extern __shared__ float sm[];
    float* At = sm;                 // [k 0..63][row 0..127] transposed
    float* Vs = sm + 64 * ATSTR;    // [k][d]
    int mb = blockIdx.x * 128;
    int bh = blockIdx.y;
    int kz = blockIdx.z << 8;       // z * 256
    int tid = threadIdx.x;
    int ty = tid >> 4, tx = tid & 15;

    u64 acc[4][4];
#pragma unroll
    for (int i = 0; i < 4; i++)
#pragma unroll
        for (int j = 0; j < 4; j++) acc[i][j] = 0ULL;

    for (int k0 = 0; k0 < 256; k0 += 64) {
        {   // fill At transposed: At[k][row]
            int row = tid >> 1;
            int c0 = (tid & 1) << 5;
            const float* ap = attn + (size_t)(bh * 1024 + mb + row) * 1024 + kz + k0 + c0;
#pragma unroll
            for (int m = 0; m < 8; m++) {
                float4 av = *(const float4*)(ap + m * 4);
                int kk = c0 + m * 4;
                At[(kk + 0) * ATSTR + row] = av.x;
                At[(kk + 1) * ATSTR + row] = av.y;
                At[(kk + 2) * ATSTR + row] = av.z;
                At[(kk + 3) * ATSTR + row] = av.w;
            }
        }
        {   // fill Vs natural: Vs[k][d]
            int vr = tid >> 2;
            int d0 = (tid & 3) << 4;
            const float* vp = g_v + (size_t)(bh * 1024 + kz + k0 + vr) * 64 + d0;
            float* vd = Vs + vr * VSTR2 + d0;
#pragma unroll
            for (int m = 0; m < 4; m++)
                *(float4*)(vd + m * 4) = *(const float4*)(vp + m * 4);
        }
        __syncthreads();

#pragma unroll 8
        for (int kk = 0; kk < 64; kk++) {
            u64x2 a01 = *(const u64x2*)(At + kk * ATSTR + ty * 8);      // rows 0-3 (2 pairs)
            u64x2 a23 = *(const u64x2*)(At + kk * ATSTR + ty * 8 + 4);  // rows 4-7 (2 pairs)
            float4 bf = *(const float4*)(Vs + kk * VSTR2 + tx * 4);
            u64 ap4[4] = {a01.x, a01.y, a23.x, a23.y};
            u64 bp4[4] = {dup2(bf.x), dup2(bf.y), dup2(bf.z), dup2(bf.w)};
#pragma unroll
            for (int i = 0; i < 4; i++)
#pragma unroll
                for (int j = 0; j < 4; j++) acc[i][j] = f2fma(ap4[i], bp4[j], acc[i][j]);
        }
        __syncthreads();
    }

    int b = bh >> 3, h = bh & 7;
    float* base = g_aoP + (size_t)blockIdx.z * (Mq * Cq);
#pragma unroll
    for (int p = 0; p < 4; p++) {
        float2 v0 = upk(acc[p][0]);
        float2 v1 = upk(acc[p][1]);
        float2 v2 = upk(acc[p][2]);
        float2 v3 = upk(acc[p][3]);
        float4 lo = {v0.x, v1.x, v2.x, v3.x};   // row 2p
        float4 hi = {v0.y, v1.y, v2.y, v3.y};   // row 2p+1
        int n0 = mb + ty * 8 + 2 * p;
        *(float4*)(base + (size_t)(b * 1024 + n0) * 512 + h * 64 + tx * 4) = lo;
        *(float4*)(base + (size_t)(b * 1024 + n0 + 1) * 512 + h * 64 + tx * 4) = hi;
    }
}

// ---------------------------------------------------------------------------
// Kernel 5: proj GEMM + bias + residual. A = sum of 4 g_aoP partials.
// 128x128x8 tiles, double-buffered, FFMA2 inner.
// ---------------------------------------------------------------------------
__global__ __launch_bounds__(256) void k_proj(const float* __restrict__ x,
                                              const float* __restrict__ Bm,
                                              const float* __restrict__ bias) {
    const int K = 512, Nn = 512;
    const int P = Mq * Cq;
    __shared__ float As[2][8][128];
    __shared__ float Bs[2][8][128];
    int tid = threadIdx.x;
    int bx = blockIdx.x, by = blockIdx.y;
    int aRow = tid >> 1, aCol = (tid & 1) << 2;
    int bRow = tid >> 5, bCol = (tid & 31) << 2;
    int ty = tid >> 4, tx = tid & 15;

    u64 acc[8][4];
#pragma unroll
    for (int i = 0; i < 8; i++)
#pragma unroll
        for (int j = 0; j < 4; j++) acc[i][j] = 0ULL;

    const float* Ap = g_aoP + (size_t)(by * 128 + aRow) * K + aCol;
    const float* Bp = Bm + (size_t)bRow * Nn + bx * 128 + bCol;

    {
        float4 a0 = *(const float4*)(Ap);
        float4 a1 = *(const float4*)(Ap + P);
        float4 a2 = *(const float4*)(Ap + 2 * P);
        float4 a3 = *(const float4*)(Ap + 3 * P);
        float4 av = {a0.x + a1.x + a2.x + a3.x, a0.y + a1.y + a2.y + a3.y,
                     a0.z + a1.z + a2.z + a3.z, a0.w + a1.w + a2.w + a3.w};
        As[0][aCol + 0][aRow] = av.x;
        As[0][aCol + 1][aRow] = av.y;
        As[0][aCol + 2][aRow] = av.z;
        As[0][aCol + 3][aRow] = av.w;
        *(float4*)&Bs[0][bRow][bCol] = *(const float4*)(Bp);
    }
    __syncthreads();

    for (int k0 = 0; k0 < K; k0 += 8) {
        int buf = (k0 >> 3) & 1;
        float4 av, bv;
        bool more = (k0 + 8) < K;
        if (more) {
            float4 a0 = *(const float4*)(Ap + k0 + 8);
            float4 a1 = *(const float4*)(Ap + P + k0 + 8);
            float4 a2 = *(const float4*)(Ap + 2 * P + k0 + 8);
            float4 a3 = *(const float4*)(Ap + 3 * P + k0 + 8);
            av.x = a0.x + a1.x + a2.x + a3.x;
            av.y = a0.y + a1.y + a2.y + a3.y;
            av.z = a0.z + a1.z + a2.z + a3.z;
            av.w = a0.w + a1.w + a2.w + a3.w;
            bv = *(const float4*)(Bp + (size_t)(k0 + 8) * Nn);
        }
#pragma unroll
        for (int k = 0; k < 8; k++) {
            float a[8];
            *(float4*)&a[0] = *(const float4*)&As[buf][k][ty * 8];
            *(float4*)&a[4] = *(const float4*)&As[buf][k][ty * 8 + 4];
            u64x2 b0 = *(const u64x2*)&Bs[buf][k][tx * 8];
            u64x2 b1 = *(const u64x2*)&Bs[buf][k][tx * 8 + 4];
            u64 bp[4] = {b0.x, b0.y, b1.x, b1.y};
#pragma unroll
            for (int i = 0; i < 8; i++) {
                u64 ad = dup2(a[i]);
#pragma unroll
                for (int j = 0; j < 4; j++) acc[i][j] = f2fma(ad, bp[j], acc[i][j]);
            }
        }
        if (more) {
            int nb2 = buf ^ 1;
            As[nb2][aCol + 0][aRow] = av.x;
            As[nb2][aCol + 1][aRow] = av.y;
            As[nb2][aCol + 2][aRow] = av.z;
            As[nb2][aCol + 3][aRow] = av.w;
            *(float4*)&Bs[nb2][bRow][bCol] = bv;
        }
        __syncthreads();
    }

#pragma unroll
    for (int i = 0; i < 8; i++) {
        int r = by * 128 + ty * 8 + i;
#pragma unroll
        for (int jp = 0; jp < 4; jp++) {
            float2 v2 = upk(acc[i][jp]);
            int c = bx * 128 + tx * 8 + jp * 2;
            g_yp[(size_t)r * 512 + c]     = v2.x + bias[c]     + x[(size_t)r * 512 + c];
            g_yp[(size_t)r * 512 + c + 1] = v2.y + bias[c + 1] + x[(size_t)r * 512 + c + 1];
        }
    }
}

// ---------------------------------------------------------------------------
// Kernel 6: LayerNorm over last dim (512), write y to d_out.
// ---------------------------------------------------------------------------
__global__ __launch_bounds__(128) void k_ln(const float* __restrict__ gamma,
                                            const float* __restrict__ beta,
                                            float* __restrict__ y) {
    __shared__ float s1[4], s2[4];
    int row = blockIdx.x;
    int tid = threadIdx.x;
    const float* p = g_yp + (size_t)row * 512;
    float4 v = *(const float4*)(p + tid * 4);

    float s = v.x + v.y + v.z + v.w;
    float ss = v.x * v.x + v.y * v.y + v.z * v.z + v.w * v.w;
#pragma unroll
    for (int o = 16; o; o >>= 1) {
        s += __shfl_xor_sync(0xffffffffu, s, o);
        ss += __shfl_xor_sync(0xffffffffu, ss, o);
    }
    int wid = tid >> 5, lane = tid & 31;
    if (lane == 0) { s1[wid] = s; s2[wid] = ss; }
    __syncthreads();
    if (tid == 0) {
        s1[0] = s1[0] + s1[1] + s1[2] + s1[3];
        s2[0] = s2[0] + s2[1] + s2[2] + s2[3];
    }
    __syncthreads();
    float mu = s1[0] * (1.f / 512.f);
    float var = s2[0] * (1.f / 512.f) - mu * mu;
    float rstd = rsqrtf(var + LN_EPSq);

    int c = tid * 4;
    float4 g = *(const float4*)(gamma + c);
    float4 be = *(const float4*)(beta + c);
    float4 o;
    o.x = (v.x - mu) * rstd * g.x + be.x;
    o.y = (v.y - mu) * rstd * g.y + be.y;
    o.z = (v.z - mu) * rstd * g.z + be.z;
    o.w = (v.w - mu) * rstd * g.w + be.w;
    *(float4*)(y + (size_t)row * 512 + c) = o;
}

// ---------------------------------------------------------------------------
extern "C" void kernel_launch(void* const* d_in, const int* in_sizes, int n_in,
                              void* d_out, int out_size) {
    (void)in_sizes; (void)n_in; (void)out_size;
    const float* x     = (const float*)d_in[0];
    const float* Wqkv  = (const float*)d_in[1];
    const float* bqkv  = (const float*)d_in[2];
    const float* ow    = (const float*)d_in[3];
    const float* Wproj = (const float*)d_in[4];
    const float* bproj = (const float*)d_in[5];
    const float* gamma = (const float*)d_in[6];
    const float* beta  = (const float*)d_in[7];

    float* out      = (float*)d_out;
    float* y_out    = out;                         // [4,1024,512]
    float* attn_out = out + (size_t)Bq * Nq * Cq;  // [4,8,1024,1024]

    int scores_smem = 2 * 64 * QKSTR * (int)sizeof(float);          // 67584 B
    int av_smem     = (64 * ATSTR + 64 * VSTR2) * (int)sizeof(float); // 51200 B
    cudaFuncSetAttribute(k_scores, cudaFuncAttributeMaxDynamicSharedMemorySize,
                         scores_smem);
    cudaFuncSetAttribute(k_av, cudaFuncAttributeMaxDynamicSharedMemorySize,
                         av_smem);

    k_qkv    <<<dim3(12, 32), 256>>>(x, Wqkv, bqkv);
    k_scores <<<dim3(8, 8, 32), 256, scores_smem>>>(ow, attn_out);
    k_softmax<<<32768, 256>>>(attn_out);
    k_av     <<<dim3(8, 32, 4), 256, av_smem>>>(attn_out);
    k_proj   <<<dim3(4, 32), 256>>>(x, Wproj, bproj);
    k_ln     <<<4096, 128>>>(gamma, beta, y_out);
}